// round 14
// baseline (speedup 1.0000x reference)
#include <cuda_runtime.h>

// ============================================================================
// Compile-time Clebsch-Gordan machinery (Condon-Shortley, real SH basis),
// faithful to the reference's _cg_complex / _u / _cg_real.
// ============================================================================
namespace cgc {

__host__ __device__ constexpr double cfact(int n) {
    double r = 1.0;
    for (int i = 2; i <= n; ++i) r *= (double)i;
    return r;
}

__host__ __device__ constexpr double csqrt(double x) {
    if (x <= 0.0) return 0.0;
    double r = x > 1.0 ? x : 1.0;
    for (int i = 0; i < 200; ++i) {
        double nr = 0.5 * (r + x / r);
        if (nr == r) break;
        r = nr;
    }
    return r;
}

__host__ __device__ constexpr double cg_complex(int l1, int l2, int l3, int m1, int m2) {
    int m3 = m1 + m2;
    if (m3 < -l3 || m3 > l3) return 0.0;
    double pre = csqrt((2 * l3 + 1) * cfact(l1 + l2 - l3) * cfact(l1 - l2 + l3) *
                       cfact(-l1 + l2 + l3) / cfact(l1 + l2 + l3 + 1));
    pre *= csqrt(cfact(l3 + m3) * cfact(l3 - m3) * cfact(l1 - m1) * cfact(l1 + m1) *
                 cfact(l2 - m2) * cfact(l2 + m2));
    double s = 0.0;
    for (int k = 0; k <= l1 + l2 - l3; ++k) {
        int d1 = k, d2 = l1 + l2 - l3 - k, d3 = l1 - m1 - k, d4 = l2 + m2 - k;
        int d5 = l3 - l2 + m1 + k, d6 = l3 - l1 - m2 + k;
        if (d1 < 0 || d2 < 0 || d3 < 0 || d4 < 0 || d5 < 0 || d6 < 0) continue;
        double den = cfact(d1) * cfact(d2) * cfact(d3) * cfact(d4) * cfact(d5) * cfact(d6);
        s += ((k & 1) ? -1.0 : 1.0) / den;
    }
    return pre * s;
}

__host__ __device__ constexpr double u_re(int l, int a, int i) {
    int mr = a - l, mc = i - l;
    double inv = 1.0 / csqrt(2.0);
    if (mr == 0) return (mc == 0) ? 1.0 : 0.0;
    if (mr > 0) {
        if (mc == mr)  return ((mr & 1) ? -inv : inv);
        if (mc == -mr) return inv;
    }
    return 0.0;
}
__host__ __device__ constexpr double u_im(int l, int a, int i) {
    int mr = a - l, mc = i - l;
    double inv = 1.0 / csqrt(2.0);
    if (mr < 0) {
        int m = -mr;
        if (mc == -m) return inv;
        if (mc == m)  return ((m & 1) ? inv : -inv);
    }
    return 0.0;
}

__host__ __device__ constexpr double cg_real(int l1, int l2, int l3, int a, int b, int c) {
    double re = 0.0, im = 0.0;
    for (int i = 0; i < 2 * l1 + 1; ++i) {
        for (int j = 0; j < 2 * l2 + 1; ++j) {
            int k = (i - l1) + (j - l2) + l3;
            if (k < 0 || k > 2 * l3) continue;
            double Cv = cg_complex(l1, l2, l3, i - l1, j - l2);
            if (Cv == 0.0) continue;
            double u1r = u_re(l1, a, i), u1i = u_im(l1, a, i);
            double u2r = u_re(l2, b, j), u2i = u_im(l2, b, j);
            double u3r = u_re(l3, c, k), u3i = -u_im(l3, c, k);
            double pr = u1r * u2r - u1i * u2i;
            double pi = u1r * u2i + u1i * u2r;
            double rr = pr * u3r - pi * u3i;
            double ri = pr * u3i + pi * u3r;
            re += rr * Cv;
            im += ri * Cv;
        }
    }
    return (((l1 + l2 + l3) & 1) ? im : re);
}

__host__ __device__ constexpr bool pair_used(int l1, int l2, int l3, int i, int j) {
    for (int k = 0; k < 2 * l3 + 1; ++k) {
        double v = cg_real(l1, l2, l3, i, j, k);
        if (v > 1e-9 || v < -1e-9) return true;
    }
    return false;
}

}  // namespace cgc

// ============================================================================
// 2-wide lanes with streaming cache policy on the bulk streams.
// ============================================================================
struct f2 { float a, b; };

__device__ __forceinline__ f2 ld2s(const float* p) {
    float2 v = __ldcs(reinterpret_cast<const float2*>(p));
    return {v.x, v.y};
}
__device__ __forceinline__ f2 ld2c(const float* p) {
    float2 v = __ldg(reinterpret_cast<const float2*>(p));
    return {v.x, v.y};
}
__device__ __forceinline__ void st2s(float* p, f2 v) {
    __stcs(reinterpret_cast<float2*>(p), make_float2(v.a, v.b));
}

template <int L1, int L2, int LO, int I, int J, int K>
struct TermK {
    __device__ static __forceinline__ void run(f2 q, f2* o) {
        {
            constexpr double vd =
                cgc::cg_real(L1, L2, LO, I, J, K) * ((L1 == L2 && I < J) ? 2.0 : 1.0);
            constexpr float V = (float)vd;
            if constexpr (V > 1e-7f || V < -1e-7f) {
                o[K].a = fmaf(V, q.a, o[K].a);
                o[K].b = fmaf(V, q.b, o[K].b);
            }
        }
        if constexpr (K + 1 <= 2 * LO) TermK<L1, L2, LO, I, J, K + 1>::run(q, o);
    }
};

template <int L1, int L2, int LO, int I, int J>
struct PairLoop {
    __device__ static __forceinline__ void run(const f2* xa, const f2* xb, f2 s, f2* o) {
        if constexpr (cgc::pair_used(L1, L2, LO, I, J)) {
            f2 q;
            q.a = (xa[I].a * xb[J].a) * s.a;
            q.b = (xa[I].b * xb[J].b) * s.b;
            TermK<L1, L2, LO, I, J, 0>::run(q, o);
        }
        if constexpr (J < 2 * L2) {
            PairLoop<L1, L2, LO, I, J + 1>::run(xa, xb, s, o);
        } else if constexpr (I < 2 * L1) {
            PairLoop<L1, L2, LO, I + 1, (L1 == L2 ? I + 1 : 0)>::run(xa, xb, s, o);
        }
    }
};

// ============================================================================
// Kernel: one thread per (batch row, channel pair) — the proven-best R9/R13
// structure — registers capped at 64 (__launch_bounds__(256, 4)) to fit
// 4 CTAs/SM (occ 30.5% -> ~41%). At 84-cap ptxas used only 80 regs, so there
// is slack to squeeze; widest phase truly needs ~46-50 live regs.
//
// Output groups computed AND stored one lout at a time (caps live registers,
// drains stores early). Coefficients loaded just-in-time per group.
//
// Coupling algebra (derived R0):
//   - antisymmetric self-couplings (1,1|1),(2,2|1),(2,2|3) vanish exactly
//   - swap pairs merged with parity sign: rows 3+4, 6+7, 9+12, 11-13, 15+16
// ============================================================================
__global__ void __launch_bounds__(256, 4) selfmix_kernel(
    const float* __restrict__ x, const float* __restrict__ keep,
    const float* __restrict__ mix, float* __restrict__ out, int B) {
    const int cp = threadIdx.x & 63;
    const int b = blockIdx.x * 4 + (threadIdx.x >> 6);
    if (b >= B) return;
    const int c2 = cp * 2;

    const float* xb = x + (long long)b * 1152 + c2;
    f2 x0[1], x1[3], x2[5];
    x0[0] = ld2s(xb);
#pragma unroll
    for (int m = 0; m < 3; ++m) x1[m] = ld2s(xb + 128 + m * 128);
#pragma unroll
    for (int m = 0; m < 5; ++m) x2[m] = ld2s(xb + 512 + m * 128);

    float* ob = out + (long long)b * 3200 + c2;

    // ---- lout = 4 : (2,2|4) ----
    {
        f2 s224 = ld2c(mix + 18 * 128 + c2);
        s224.a *= 0.5f; s224.b *= 0.5f;
        f2 o4[9];
#pragma unroll
        for (int m = 0; m < 9; ++m) o4[m] = {0.f, 0.f};
        PairLoop<2, 2, 4, 0, 0>::run(x2, x2, s224, o4);
#pragma unroll
        for (int m = 0; m < 9; ++m) st2s(ob + 2048 + m * 128, o4[m]);
    }

    // ---- lout = 3 : (1,2|3)+(2,1|3) merged ----
    {
        f2 ma = ld2c(mix + 15 * 128 + c2), mb = ld2c(mix + 16 * 128 + c2);
        f2 s123 = {0.5f * (ma.a + mb.a), 0.5f * (ma.b + mb.b)};
        f2 o3[7];
#pragma unroll
        for (int m = 0; m < 7; ++m) o3[m] = {0.f, 0.f};
        PairLoop<1, 2, 3, 0, 0>::run(x1, x2, s123, o3);
#pragma unroll
        for (int m = 0; m < 7; ++m) st2s(ob + 1152 + m * 128, o3[m]);
    }

    // ---- lout = 2 : keep + (0,2)+(2,0), (1,1), (1,2)-(2,1), (2,2) ----
    {
        f2 k2 = ld2c(keep + 256 + c2);
        f2 o2[5];
#pragma unroll
        for (int m = 0; m < 5; ++m)
            o2[m] = {k2.a * x2[m].a, k2.b * x2[m].b};
        f2 ma, mb;
        ma = ld2c(mix + 9 * 128 + c2);  mb = ld2c(mix + 12 * 128 + c2);
        f2 s022 = {0.5f * (ma.a + mb.a), 0.5f * (ma.b + mb.b)};
        PairLoop<0, 2, 2, 0, 0>::run(x0, x2, s022, o2);
        ma = ld2c(mix + 10 * 128 + c2);
        f2 s112 = {0.5f * ma.a, 0.5f * ma.b};
        PairLoop<1, 1, 2, 0, 0>::run(x1, x1, s112, o2);
        ma = ld2c(mix + 11 * 128 + c2); mb = ld2c(mix + 13 * 128 + c2);
        f2 s122 = {0.5f * (ma.a - mb.a), 0.5f * (ma.b - mb.b)};
        PairLoop<1, 2, 2, 0, 0>::run(x1, x2, s122, o2);
        ma = ld2c(mix + 14 * 128 + c2);
        f2 s222 = {0.5f * ma.a, 0.5f * ma.b};
        PairLoop<2, 2, 2, 0, 0>::run(x2, x2, s222, o2);
#pragma unroll
        for (int m = 0; m < 5; ++m) st2s(ob + 512 + m * 128, o2[m]);
    }

    // ---- lout = 1 : keep + (0,1)+(1,0), (1,2)+(2,1) ----
    {
        f2 k1 = ld2c(keep + 128 + c2);
        f2 o1[3];
#pragma unroll
        for (int m = 0; m < 3; ++m)
            o1[m] = {k1.a * x1[m].a, k1.b * x1[m].b};
        f2 ma, mb;
        ma = ld2c(mix + 3 * 128 + c2); mb = ld2c(mix + 4 * 128 + c2);
        f2 s011 = {0.5f * (ma.a + mb.a), 0.5f * (ma.b + mb.b)};
        PairLoop<0, 1, 1, 0, 0>::run(x0, x1, s011, o1);
        ma = ld2c(mix + 6 * 128 + c2); mb = ld2c(mix + 7 * 128 + c2);
        f2 s121 = {0.5f * (ma.a + mb.a), 0.5f * (ma.b + mb.b)};
        PairLoop<1, 2, 1, 0, 0>::run(x1, x2, s121, o1);
#pragma unroll
        for (int m = 0; m < 3; ++m) st2s(ob + 128 + m * 128, o1[m]);
    }

    // ---- lout = 0 : keep + (0,0), (1,1), (2,2) ----
    {
        f2 k0 = ld2c(keep + c2);
        f2 o0[1];
        o0[0] = {k0.a * x0[0].a, k0.b * x0[0].b};
        f2 ma;
        ma = ld2c(mix + 0 * 128 + c2);
        f2 s000 = {0.5f * ma.a, 0.5f * ma.b};
        PairLoop<0, 0, 0, 0, 0>::run(x0, x0, s000, o0);
        ma = ld2c(mix + 1 * 128 + c2);
        f2 s110 = {0.5f * ma.a, 0.5f * ma.b};
        PairLoop<1, 1, 0, 0, 0>::run(x1, x1, s110, o0);
        ma = ld2c(mix + 2 * 128 + c2);
        f2 s220 = {0.5f * ma.a, 0.5f * ma.b};
        PairLoop<2, 2, 0, 0, 0>::run(x2, x2, s220, o0);
        st2s(ob, o0[0]);
    }
}

extern "C" void kernel_launch(void* const* d_in, const int* in_sizes, int n_in,
                              void* d_out, int out_size) {
    const float* x = nullptr;
    const float* keep = nullptr;
    const float* mix = nullptr;
    int bx = 0;
    for (int i = 0; i < n_in; ++i) {
        if (in_sizes[i] == 384) keep = (const float*)d_in[i];
        else if (in_sizes[i] == 2432) mix = (const float*)d_in[i];
        else { x = (const float*)d_in[i]; bx = in_sizes[i]; }
    }
    float* out = (float*)d_out;
    int B = bx / 1152;
    int blocks = (B + 3) / 4;
    selfmix_kernel<<<blocks, 256>>>(x, keep, mix, out, B);
}

// round 15
// speedup vs baseline: 1.1250x; 1.1250x over previous
#include <cuda_runtime.h>

// ============================================================================
// Compile-time Clebsch-Gordan machinery (Condon-Shortley, real SH basis),
// faithful to the reference's _cg_complex / _u / _cg_real.
// ============================================================================
namespace cgc {

__host__ __device__ constexpr double cfact(int n) {
    double r = 1.0;
    for (int i = 2; i <= n; ++i) r *= (double)i;
    return r;
}

__host__ __device__ constexpr double csqrt(double x) {
    if (x <= 0.0) return 0.0;
    double r = x > 1.0 ? x : 1.0;
    for (int i = 0; i < 200; ++i) {
        double nr = 0.5 * (r + x / r);
        if (nr == r) break;
        r = nr;
    }
    return r;
}

__host__ __device__ constexpr double cg_complex(int l1, int l2, int l3, int m1, int m2) {
    int m3 = m1 + m2;
    if (m3 < -l3 || m3 > l3) return 0.0;
    double pre = csqrt((2 * l3 + 1) * cfact(l1 + l2 - l3) * cfact(l1 - l2 + l3) *
                       cfact(-l1 + l2 + l3) / cfact(l1 + l2 + l3 + 1));
    pre *= csqrt(cfact(l3 + m3) * cfact(l3 - m3) * cfact(l1 - m1) * cfact(l1 + m1) *
                 cfact(l2 - m2) * cfact(l2 + m2));
    double s = 0.0;
    for (int k = 0; k <= l1 + l2 - l3; ++k) {
        int d1 = k, d2 = l1 + l2 - l3 - k, d3 = l1 - m1 - k, d4 = l2 + m2 - k;
        int d5 = l3 - l2 + m1 + k, d6 = l3 - l1 - m2 + k;
        if (d1 < 0 || d2 < 0 || d3 < 0 || d4 < 0 || d5 < 0 || d6 < 0) continue;
        double den = cfact(d1) * cfact(d2) * cfact(d3) * cfact(d4) * cfact(d5) * cfact(d6);
        s += ((k & 1) ? -1.0 : 1.0) / den;
    }
    return pre * s;
}

__host__ __device__ constexpr double u_re(int l, int a, int i) {
    int mr = a - l, mc = i - l;
    double inv = 1.0 / csqrt(2.0);
    if (mr == 0) return (mc == 0) ? 1.0 : 0.0;
    if (mr > 0) {
        if (mc == mr)  return ((mr & 1) ? -inv : inv);
        if (mc == -mr) return inv;
    }
    return 0.0;
}
__host__ __device__ constexpr double u_im(int l, int a, int i) {
    int mr = a - l, mc = i - l;
    double inv = 1.0 / csqrt(2.0);
    if (mr < 0) {
        int m = -mr;
        if (mc == -m) return inv;
        if (mc == m)  return ((m & 1) ? inv : -inv);
    }
    return 0.0;
}

__host__ __device__ constexpr double cg_real(int l1, int l2, int l3, int a, int b, int c) {
    double re = 0.0, im = 0.0;
    for (int i = 0; i < 2 * l1 + 1; ++i) {
        for (int j = 0; j < 2 * l2 + 1; ++j) {
            int k = (i - l1) + (j - l2) + l3;
            if (k < 0 || k > 2 * l3) continue;
            double Cv = cg_complex(l1, l2, l3, i - l1, j - l2);
            if (Cv == 0.0) continue;
            double u1r = u_re(l1, a, i), u1i = u_im(l1, a, i);
            double u2r = u_re(l2, b, j), u2i = u_im(l2, b, j);
            double u3r = u_re(l3, c, k), u3i = -u_im(l3, c, k);
            double pr = u1r * u2r - u1i * u2i;
            double pi = u1r * u2i + u1i * u2r;
            double rr = pr * u3r - pi * u3i;
            double ri = pr * u3i + pi * u3r;
            re += rr * Cv;
            im += ri * Cv;
        }
    }
    return (((l1 + l2 + l3) & 1) ? im : re);
}

__host__ __device__ constexpr bool pair_used(int l1, int l2, int l3, int i, int j) {
    for (int k = 0; k < 2 * l3 + 1; ++k) {
        double v = cg_real(l1, l2, l3, i, j, k);
        if (v > 1e-9 || v < -1e-9) return true;
    }
    return false;
}

}  // namespace cgc

// ============================================================================
// 2-wide lanes with streaming cache policy on the bulk streams.
// ============================================================================
struct f2 { float a, b; };

__device__ __forceinline__ f2 ld2s(const float* p) {
    float2 v = __ldcs(reinterpret_cast<const float2*>(p));
    return {v.x, v.y};
}
__device__ __forceinline__ f2 ld2c(const float* p) {
    float2 v = __ldg(reinterpret_cast<const float2*>(p));
    return {v.x, v.y};
}
__device__ __forceinline__ void st2s(float* p, f2 v) {
    __stcs(reinterpret_cast<float2*>(p), make_float2(v.a, v.b));
}

template <int L1, int L2, int LO, int I, int J, int K>
struct TermK {
    __device__ static __forceinline__ void run(f2 q, f2* o) {
        {
            constexpr double vd =
                cgc::cg_real(L1, L2, LO, I, J, K) * ((L1 == L2 && I < J) ? 2.0 : 1.0);
            constexpr float V = (float)vd;
            if constexpr (V > 1e-7f || V < -1e-7f) {
                o[K].a = fmaf(V, q.a, o[K].a);
                o[K].b = fmaf(V, q.b, o[K].b);
            }
        }
        if constexpr (K + 1 <= 2 * LO) TermK<L1, L2, LO, I, J, K + 1>::run(q, o);
    }
};

template <int L1, int L2, int LO, int I, int J>
struct PairLoop {
    __device__ static __forceinline__ void run(const f2* xa, const f2* xb, f2 s, f2* o) {
        if constexpr (cgc::pair_used(L1, L2, LO, I, J)) {
            f2 q;
            q.a = (xa[I].a * xb[J].a) * s.a;
            q.b = (xa[I].b * xb[J].b) * s.b;
            TermK<L1, L2, LO, I, J, 0>::run(q, o);
        }
        if constexpr (J < 2 * L2) {
            PairLoop<L1, L2, LO, I, J + 1>::run(xa, xb, s, o);
        } else if constexpr (I < 2 * L1) {
            PairLoop<L1, L2, LO, I + 1, (L1 == L2 ? I + 1 : 0)>::run(xa, xb, s, o);
        }
    }
};

// ============================================================================
// FINAL (= R13 measured-best): one thread per (batch row, channel pair),
// 64 threads span 128 channels, 256-thread block covers 4 rows.
// __launch_bounds__(256, 3): 84-reg cap -> ptxas uses 80, no spill, 3 CTAs/SM
// (the measured optimum of the regs/occupancy tradeoff; 64-reg cap spills,
// no cap wastes occupancy at 108 regs).
//
// Output groups computed AND stored one lout at a time (caps live registers,
// drains stores early). Coefficients loaded just-in-time per group.
//
// Coupling algebra (derived R0):
//   - antisymmetric self-couplings (1,1|1),(2,2|1),(2,2|3) vanish exactly
//   - swap pairs merged with parity sign: rows 3+4, 6+7, 9+12, 11-13, 15+16
//
// Measured: kernel 42.18us, DRAM 67.8%, effective unique-traffic throughput
// 6.76 TB/s (~85% of HBM spec) — converged at the mixed-stream roofline.
// ============================================================================
__global__ void __launch_bounds__(256, 3) selfmix_kernel(
    const float* __restrict__ x, const float* __restrict__ keep,
    const float* __restrict__ mix, float* __restrict__ out, int B) {
    const int cp = threadIdx.x & 63;
    const int b = blockIdx.x * 4 + (threadIdx.x >> 6);
    if (b >= B) return;
    const int c2 = cp * 2;

    const float* xb = x + (long long)b * 1152 + c2;
    f2 x0[1], x1[3], x2[5];
    x0[0] = ld2s(xb);
#pragma unroll
    for (int m = 0; m < 3; ++m) x1[m] = ld2s(xb + 128 + m * 128);
#pragma unroll
    for (int m = 0; m < 5; ++m) x2[m] = ld2s(xb + 512 + m * 128);

    float* ob = out + (long long)b * 3200 + c2;

    // ---- lout = 4 : (2,2|4) ----
    {
        f2 s224 = ld2c(mix + 18 * 128 + c2);
        s224.a *= 0.5f; s224.b *= 0.5f;
        f2 o4[9];
#pragma unroll
        for (int m = 0; m < 9; ++m) o4[m] = {0.f, 0.f};
        PairLoop<2, 2, 4, 0, 0>::run(x2, x2, s224, o4);
#pragma unroll
        for (int m = 0; m < 9; ++m) st2s(ob + 2048 + m * 128, o4[m]);
    }

    // ---- lout = 3 : (1,2|3)+(2,1|3) merged ----
    {
        f2 ma = ld2c(mix + 15 * 128 + c2), mb = ld2c(mix + 16 * 128 + c2);
        f2 s123 = {0.5f * (ma.a + mb.a), 0.5f * (ma.b + mb.b)};
        f2 o3[7];
#pragma unroll
        for (int m = 0; m < 7; ++m) o3[m] = {0.f, 0.f};
        PairLoop<1, 2, 3, 0, 0>::run(x1, x2, s123, o3);
#pragma unroll
        for (int m = 0; m < 7; ++m) st2s(ob + 1152 + m * 128, o3[m]);
    }

    // ---- lout = 2 : keep + (0,2)+(2,0), (1,1), (1,2)-(2,1), (2,2) ----
    {
        f2 k2 = ld2c(keep + 256 + c2);
        f2 o2[5];
#pragma unroll
        for (int m = 0; m < 5; ++m)
            o2[m] = {k2.a * x2[m].a, k2.b * x2[m].b};
        f2 ma, mb;
        ma = ld2c(mix + 9 * 128 + c2);  mb = ld2c(mix + 12 * 128 + c2);
        f2 s022 = {0.5f * (ma.a + mb.a), 0.5f * (ma.b + mb.b)};
        PairLoop<0, 2, 2, 0, 0>::run(x0, x2, s022, o2);
        ma = ld2c(mix + 10 * 128 + c2);
        f2 s112 = {0.5f * ma.a, 0.5f * ma.b};
        PairLoop<1, 1, 2, 0, 0>::run(x1, x1, s112, o2);
        ma = ld2c(mix + 11 * 128 + c2); mb = ld2c(mix + 13 * 128 + c2);
        f2 s122 = {0.5f * (ma.a - mb.a), 0.5f * (ma.b - mb.b)};
        PairLoop<1, 2, 2, 0, 0>::run(x1, x2, s122, o2);
        ma = ld2c(mix + 14 * 128 + c2);
        f2 s222 = {0.5f * ma.a, 0.5f * ma.b};
        PairLoop<2, 2, 2, 0, 0>::run(x2, x2, s222, o2);
#pragma unroll
        for (int m = 0; m < 5; ++m) st2s(ob + 512 + m * 128, o2[m]);
    }

    // ---- lout = 1 : keep + (0,1)+(1,0), (1,2)+(2,1) ----
    {
        f2 k1 = ld2c(keep + 128 + c2);
        f2 o1[3];
#pragma unroll
        for (int m = 0; m < 3; ++m)
            o1[m] = {k1.a * x1[m].a, k1.b * x1[m].b};
        f2 ma, mb;
        ma = ld2c(mix + 3 * 128 + c2); mb = ld2c(mix + 4 * 128 + c2);
        f2 s011 = {0.5f * (ma.a + mb.a), 0.5f * (ma.b + mb.b)};
        PairLoop<0, 1, 1, 0, 0>::run(x0, x1, s011, o1);
        ma = ld2c(mix + 6 * 128 + c2); mb = ld2c(mix + 7 * 128 + c2);
        f2 s121 = {0.5f * (ma.a + mb.a), 0.5f * (ma.b + mb.b)};
        PairLoop<1, 2, 1, 0, 0>::run(x1, x2, s121, o1);
#pragma unroll
        for (int m = 0; m < 3; ++m) st2s(ob + 128 + m * 128, o1[m]);
    }

    // ---- lout = 0 : keep + (0,0), (1,1), (2,2) ----
    {
        f2 k0 = ld2c(keep + c2);
        f2 o0[1];
        o0[0] = {k0.a * x0[0].a, k0.b * x0[0].b};
        f2 ma;
        ma = ld2c(mix + 0 * 128 + c2);
        f2 s000 = {0.5f * ma.a, 0.5f * ma.b};
        PairLoop<0, 0, 0, 0, 0>::run(x0, x0, s000, o0);
        ma = ld2c(mix + 1 * 128 + c2);
        f2 s110 = {0.5f * ma.a, 0.5f * ma.b};
        PairLoop<1, 1, 0, 0, 0>::run(x1, x1, s110, o0);
        ma = ld2c(mix + 2 * 128 + c2);
        f2 s220 = {0.5f * ma.a, 0.5f * ma.b};
        PairLoop<2, 2, 0, 0, 0>::run(x2, x2, s220, o0);
        st2s(ob, o0[0]);
    }
}

extern "C" void kernel_launch(void* const* d_in, const int* in_sizes, int n_in,
                              void* d_out, int out_size) {
    const float* x = nullptr;
    const float* keep = nullptr;
    const float* mix = nullptr;
    int bx = 0;
    for (int i = 0; i < n_in; ++i) {
        if (in_sizes[i] == 384) keep = (const float*)d_in[i];
        else if (in_sizes[i] == 2432) mix = (const float*)d_in[i];
        else { x = (const float*)d_in[i]; bx = in_sizes[i]; }
    }
    float* out = (float*)d_out;
    int B = bx / 1152;
    int blocks = (B + 3) / 4;
    selfmix_kernel<<<blocks, 256>>>(x, keep, mix, out, B);
}